// round 11
// baseline (speedup 1.0000x reference)
#include <cuda_runtime.h>
#include <cuda_bf16.h>
#include <cstdint>

#define NBLK 128
#define NTHR 256
typedef unsigned u32;
typedef unsigned long long u64;

// -------- device scratch --------
__device__ float d_XP[(size_t)64 * 512 * 3072];   // x-projections (+bias) [b*512+s][3072]
__device__ float d_hF[2][1024 * 64];              // h fp32 [col][b], double buffered
__device__ unsigned short d_hHi[64 * 1024], d_hLo[64 * 1024];    // h split bf16 [b][k]
__device__ unsigned short d_rhHi[64 * 1024], d_rhLo[64 * 1024];  // r*h split bf16 [b][k]
__device__ float d_pA[(size_t)4 * 2048 * 64];     // phase-A partials [p][col][b] (z:0-1023, r:1024-2047)
__device__ float d_pB[(size_t)8 * 1024 * 64];     // phase-B partials [p][col][b]
__device__ unsigned d_count;

// -------- helpers --------
__device__ __forceinline__ u64 dup2(float x){u64 r;asm("mov.b64 %0,{%1,%1};":"=l"(r):"f"(x));return r;}
__device__ __forceinline__ void fma2(u64&a,u64 x,u64 y){asm("fma.rn.f32x2 %0,%1,%2,%0;":"+l"(a):"l"(x),"l"(y));}
__device__ __forceinline__ float2 unp2(u64 v){float2 f;asm("mov.b64 {%0,%1},%2;":"=f"(f.x),"=f"(f.y):"l"(v));return f;}
__device__ __forceinline__ void lds128(u64&a,u64&b,unsigned ad){asm volatile("ld.shared.v2.u64 {%0,%1},[%2];":"=l"(a),"=l"(b):"r"(ad));}
__device__ __forceinline__ float sigmoidf(float x){return 1.f/(1.f+__expf(-x));}

__device__ __forceinline__ void mma_bf16(float* c,const u32* a,const u32* b){
    asm volatile("mma.sync.aligned.m16n8k16.row.col.f32.bf16.bf16.f32 "
        "{%0,%1,%2,%3},{%4,%5,%6,%7},{%8,%9},{%0,%1,%2,%3};"
        : "+f"(c[0]),"+f"(c[1]),"+f"(c[2]),"+f"(c[3])
        : "r"(a[0]),"r"(a[1]),"r"(a[2]),"r"(a[3]),"r"(b[0]),"r"(b[1]));
}
__device__ __forceinline__ unsigned short bfhi(float x){
    return __bfloat16_as_ushort(__float2bfloat16(x));
}
__device__ __forceinline__ unsigned short bflo(float x){
    float h=__bfloat162float(__float2bfloat16(x));
    return __bfloat16_as_ushort(__float2bfloat16(x-h));
}

// release-atomic grid barrier (monotone; safe across launches/replays)
__device__ __forceinline__ void gridbar(){
    __syncthreads();
    if(threadIdx.x==0){
        unsigned a;
        asm volatile("atom.add.release.gpu.u32 %0,[%1],%2;"
                     :"=r"(a):"l"(&d_count),"r"(1u):"memory");
        unsigned tg=a-(a&(NBLK-1))+NBLK,cur;
        do{asm volatile("ld.acquire.gpu.u32 %0,[%1];":"=r"(cur):"l"(&d_count));}while((int)(cur-tg)<0);
    }
    __syncthreads();
}

// -------- xproj (fp32, proven) --------
__global__ void __launch_bounds__(256) xproj_kernel(
    const float* __restrict__ x,
    const float* __restrict__ Wxz,const float* __restrict__ Wxr,const float* __restrict__ Wxh,
    const float* __restrict__ bz,const float* __restrict__ br,const float* __restrict__ bh){
    __shared__ float As[64*68],Bs[64*68];
    const int tid=threadIdx.x,ct=blockIdx.x,rt=blockIdx.y,wsel=ct>>4;
    const float* W=(wsel==0)?Wxz:((wsel==1)?Wxr:Wxh);
    const float* bias=(wsel==0)?bz:((wsel==1)?br:bh);
    const int colbase=(ct&15)*64,row0=rt*64,r4=(tid>>4)*4,c4=(tid&15)*4;
    u64 acc[4][2]={};
    for(int k0=0;k0<256;k0+=64){
        __syncthreads();
#pragma unroll
        for(int i=0;i<4;i++){int q=tid+i*256,rr=q>>4,kq=q&15;
            *(float4*)&As[rr*68+kq*4]=*(const float4*)&x[(size_t)(row0+rr)*256+k0+kq*4];}
#pragma unroll
        for(int i=0;i<4;i++){int q=tid+i*256,kk=q>>4,cq=q&15;
            *(float4*)&Bs[kk*68+cq*4]=*(const float4*)&W[(size_t)(k0+kk)*1024+colbase+cq*4];}
        __syncthreads();
        unsigned bs=(unsigned)__cvta_generic_to_shared(&Bs[c4]);
#pragma unroll 8
        for(int kk=0;kk<64;kk++){
            u64 bL,bH;lds128(bL,bH,bs+kk*68*4);
#pragma unroll
            for(int i=0;i<4;i++){u64 ad=dup2(As[(r4+i)*68+kk]);fma2(acc[i][0],ad,bL);fma2(acc[i][1],ad,bH);}
        }
    }
    float4 bb=*(const float4*)&bias[colbase+c4];
#pragma unroll
    for(int i=0;i<4;i++){
        float2 lo=unp2(acc[i][0]),hi=unp2(acc[i][1]);
        *(float4*)&d_XP[(size_t)(row0+r4+i)*3072+ct*64+c4]=make_float4(lo.x+bb.x,lo.y+bb.y,hi.x+bb.z,hi.y+bb.w);
    }
}

// smem (u16 units): WA hi/lo [64][264], WB hi/lo [64][136], ST hi/lo [64][264]
#define WAHI 0
#define WALO 16896
#define WBHI 33792
#define WBLO 42496
#define STHI 51200
#define STLO 68096
#define SMEM_BYTES (84992*2)

// -------- persistent GRU: HMMA split-bf16, K-split across blocks, m16n32 warps --------
__global__ void __launch_bounds__(NTHR,1) gru_kernel(
    const float* __restrict__ Whz,const float* __restrict__ Whr,
    const float* __restrict__ Whh,int s0){
    extern __shared__ unsigned short sm[];
    const int tid=threadIdx.x,bid=blockIdx.x,wid=tid>>5,lane=tid&31;
    const int cg=bid&31, kg=bid>>5;    // phase A: 32 col-groups(64) x 4 k-groups(256)
    const int cgB=bid&15,kgB=bid>>4;   // phase B: 16 col-groups(64) x 8 k-groups(128)

    // ---- load resident weight slices (split bf16, [col][k]+pad) ----
    {
        const int colg0=cg*64;
        const float* W=(colg0<1024)?(Whz+colg0):(Whr+colg0-1024);
#pragma unroll 4
        for(int i=0;i<64;i++){
            int idx=tid+i*NTHR,col=idx&63,k=idx>>6;
            float w=__ldg(&W[(size_t)(kg*256+k)*1024+col]);
            sm[WAHI+col*264+k]=bfhi(w);
            sm[WALO+col*264+k]=bflo(w);
        }
#pragma unroll 4
        for(int i=0;i<32;i++){
            int idx=tid+i*NTHR,col=idx&63,k=idx>>6;
            float w=__ldg(&Whh[(size_t)(kgB*128+k)*1024+cgB*64+col]);
            sm[WBHI+col*136+k]=bfhi(w);
            sm[WBLO+col*136+k]=bflo(w);
        }
    }
    if(s0==0){
        int gid=bid*NTHR+tid;
        ((float2*)d_hF[0])[gid]=make_float2(0.f,0.f);
        ((u32*)d_hHi)[gid]=0;((u32*)d_hLo)[gid]=0;
    }
    gridbar();

    const int mA=wid&3, nA=wid>>2;        // warp tile: m16 (cols) x n32 (batch)
    const int g=lane>>2,tk=(lane&3)*2;
    const int ecol=bid*8+wid;             // epilogue col (0..1023)
    const int eb=lane*2;                  // epilogue batch pair

    for(int s=s0;s<s0+256;s++){
        const int cur=s&1,nxt=cur^1;
        // prefetch epilogue-A operands (r-col = 1024+ecol)
        float xpr0=__ldg(&d_XP[((size_t)eb*512+s)*3072+1024+ecol]);
        float xpr1=__ldg(&d_XP[((size_t)(eb+1)*512+s)*3072+1024+ecol]);
        float2 hA=__ldcg((const float2*)&d_hF[cur][ecol*64+eb]);
        // ---- stage h slice (kg*256) ----
#pragma unroll
        for(int i=0;i<8;i++){
            int u=tid+i*NTHR,b=u>>5,ko=u&31;
            uint4 v=__ldcg((const uint4*)&d_hHi[(size_t)b*1024+kg*256+ko*8]);
            *(uint4*)&sm[STHI+b*264+ko*8]=v;
            uint4 w=__ldcg((const uint4*)&d_hLo[(size_t)b*1024+kg*256+ko*8]);
            *(uint4*)&sm[STLO+b*264+ko*8]=w;
        }
        __syncthreads();
        // ---- phase A MMA: warp m16n32, full 256-k slice, parity-split accs ----
        float acc[4][2][4];
#pragma unroll
        for(int nt=0;nt<4;nt++)
#pragma unroll
        for(int pr=0;pr<2;pr++)
#pragma unroll
        for(int q=0;q<4;q++)acc[nt][pr][q]=0.f;
#pragma unroll 1
        for(int ki=0;ki<16;ki++){
            int kk=ki*16+tk,par=ki&1;
            int r=mA*16+g;
            u32 ah[4],al[4],bh[4][2],bl[4][2];
            ah[0]=*(const u32*)&sm[WAHI+r*264+kk];
            ah[1]=*(const u32*)&sm[WAHI+(r+8)*264+kk];
            ah[2]=*(const u32*)&sm[WAHI+r*264+kk+8];
            ah[3]=*(const u32*)&sm[WAHI+(r+8)*264+kk+8];
            al[0]=*(const u32*)&sm[WALO+r*264+kk];
            al[1]=*(const u32*)&sm[WALO+(r+8)*264+kk];
            al[2]=*(const u32*)&sm[WALO+r*264+kk+8];
            al[3]=*(const u32*)&sm[WALO+(r+8)*264+kk+8];
#pragma unroll
            for(int nt=0;nt<4;nt++){
                int b=nA*32+nt*8+g;
                bh[nt][0]=*(const u32*)&sm[STHI+b*264+kk];
                bh[nt][1]=*(const u32*)&sm[STHI+b*264+kk+8];
                bl[nt][0]=*(const u32*)&sm[STLO+b*264+kk];
                bl[nt][1]=*(const u32*)&sm[STLO+b*264+kk+8];
            }
#pragma unroll
            for(int nt=0;nt<4;nt++)mma_bf16(acc[nt][par],ah,bh[nt]);
#pragma unroll
            for(int nt=0;nt<4;nt++)mma_bf16(acc[nt][par],ah,bl[nt]);
#pragma unroll
            for(int nt=0;nt<4;nt++)mma_bf16(acc[nt][par],al,bh[nt]);
        }
        {
            int colw=cg*64+mA*16+g;
            size_t base=((size_t)kg*2048+colw)*64;
#pragma unroll
            for(int nt=0;nt<4;nt++){
                int b=nA*32+nt*8+tk;
                *(float2*)&d_pA[base+b]=make_float2(acc[nt][0][0]+acc[nt][1][0],acc[nt][0][1]+acc[nt][1][1]);
                *(float2*)&d_pA[base+8*64+b]=make_float2(acc[nt][0][2]+acc[nt][1][2],acc[nt][0][3]+acc[nt][1][3]);
            }
        }
        gridbar();
        // ---- epilogue A: sum 4 r-partials -> sigmoid*h -> rh (uniform) ----
        {
            float sa=0.f,sb=0.f;
#pragma unroll
            for(int p=0;p<4;p++){
                float2 v=__ldcg((const float2*)&d_pA[((size_t)p*2048+1024+ecol)*64+eb]);
                sa+=v.x;sb+=v.y;
            }
            float r0=sigmoidf(sa+xpr0)*hA.x;
            float r1=sigmoidf(sb+xpr1)*hA.y;
            d_rhHi[(size_t)eb*1024+ecol]=bfhi(r0); d_rhLo[(size_t)eb*1024+ecol]=bflo(r0);
            d_rhHi[(size_t)(eb+1)*1024+ecol]=bfhi(r1); d_rhLo[(size_t)(eb+1)*1024+ecol]=bflo(r1);
        }
        gridbar();
        // prefetch epilogue-B operands
        float xpz0=__ldg(&d_XP[((size_t)eb*512+s)*3072+ecol]);
        float xpz1=__ldg(&d_XP[((size_t)(eb+1)*512+s)*3072+ecol]);
        float xpn0=__ldg(&d_XP[((size_t)eb*512+s)*3072+2048+ecol]);
        float xpn1=__ldg(&d_XP[((size_t)(eb+1)*512+s)*3072+2048+ecol]);
        float2 hv=__ldcg((const float2*)&d_hF[cur][ecol*64+eb]);
        // ---- stage rh slice (kgB*128) ----
#pragma unroll
        for(int i=0;i<4;i++){
            int u=tid+i*NTHR,b=u>>4,ko=u&15;
            uint4 v=__ldcg((const uint4*)&d_rhHi[(size_t)b*1024+kgB*128+ko*8]);
            *(uint4*)&sm[STHI+b*264+ko*8]=v;
            uint4 w=__ldcg((const uint4*)&d_rhLo[(size_t)b*1024+kgB*128+ko*8]);
            *(uint4*)&sm[STLO+b*264+ko*8]=w;
        }
        __syncthreads();
        // ---- phase B MMA: warp m16n32, full 128-k slice ----
        float ab[4][2][4];
#pragma unroll
        for(int nt=0;nt<4;nt++)
#pragma unroll
        for(int pr=0;pr<2;pr++)
#pragma unroll
        for(int q=0;q<4;q++)ab[nt][pr][q]=0.f;
#pragma unroll 1
        for(int ki=0;ki<8;ki++){
            int kk=ki*16+tk,par=ki&1;
            int r=mA*16+g;
            u32 ah[4],al[4],bh[4][2],bl[4][2];
            ah[0]=*(const u32*)&sm[WBHI+r*136+kk];
            ah[1]=*(const u32*)&sm[WBHI+(r+8)*136+kk];
            ah[2]=*(const u32*)&sm[WBHI+r*136+kk+8];
            ah[3]=*(const u32*)&sm[WBHI+(r+8)*136+kk+8];
            al[0]=*(const u32*)&sm[WBLO+r*136+kk];
            al[1]=*(const u32*)&sm[WBLO+(r+8)*136+kk];
            al[2]=*(const u32*)&sm[WBLO+r*136+kk+8];
            al[3]=*(const u32*)&sm[WBLO+(r+8)*136+kk+8];
#pragma unroll
            for(int nt=0;nt<4;nt++){
                int b=nA*32+nt*8+g;
                bh[nt][0]=*(const u32*)&sm[STHI+b*264+kk];
                bh[nt][1]=*(const u32*)&sm[STHI+b*264+kk+8];
                bl[nt][0]=*(const u32*)&sm[STLO+b*264+kk];
                bl[nt][1]=*(const u32*)&sm[STLO+b*264+kk+8];
            }
#pragma unroll
            for(int nt=0;nt<4;nt++)mma_bf16(ab[nt][par],ah,bh[nt]);
#pragma unroll
            for(int nt=0;nt<4;nt++)mma_bf16(ab[nt][par],ah,bl[nt]);
#pragma unroll
            for(int nt=0;nt<4;nt++)mma_bf16(ab[nt][par],al,bh[nt]);
        }
        {
            int colw=cgB*64+mA*16+g;
            size_t base=((size_t)kgB*1024+colw)*64;
#pragma unroll
            for(int nt=0;nt<4;nt++){
                int b=nA*32+nt*8+tk;
                *(float2*)&d_pB[base+b]=make_float2(ab[nt][0][0]+ab[nt][1][0],ab[nt][0][1]+ab[nt][1][1]);
                *(float2*)&d_pB[base+8*64+b]=make_float2(ab[nt][0][2]+ab[nt][1][2],ab[nt][0][3]+ab[nt][1][3]);
            }
        }
        gridbar();
        // ---- epilogue B: z from pA(4), n from pB(8), h update (uniform) ----
        {
            float z0=0.f,z1=0.f,n0=0.f,n1=0.f;
#pragma unroll
            for(int p=0;p<4;p++){
                float2 v=__ldcg((const float2*)&d_pA[((size_t)p*2048+ecol)*64+eb]);
                z0+=v.x;z1+=v.y;
            }
#pragma unroll
            for(int p=0;p<8;p++){
                float2 v=__ldcg((const float2*)&d_pB[((size_t)p*1024+ecol)*64+eb]);
                n0+=v.x;n1+=v.y;
            }
            z0=sigmoidf(z0+xpz0); z1=sigmoidf(z1+xpz1);
            n0=tanhf(n0+xpn0);    n1=tanhf(n1+xpn1);
            float h0=(1.f-z0)*hv.x+z0*n0;
            float h1=(1.f-z1)*hv.y+z1*n1;
            *(float2*)&d_hF[nxt][ecol*64+eb]=make_float2(h0,h1);
            d_hHi[(size_t)eb*1024+ecol]=bfhi(h0); d_hLo[(size_t)eb*1024+ecol]=bflo(h0);
            d_hHi[(size_t)(eb+1)*1024+ecol]=bfhi(h1); d_hLo[(size_t)(eb+1)*1024+ecol]=bflo(h1);
        }
        gridbar();
    }
}

// -------- head: out[b][o] = sum_k hF[0][k][b]*Wf[k][o] + bf[o] --------
__global__ void head_kernel(const float* __restrict__ Wf,const float* __restrict__ bf,float* __restrict__ out){
    const int b=blockIdx.x,o=threadIdx.x;
    const float* h=d_hF[0];   // after 512 steps final h is in buffer 0
    float acc=bf[o];
#pragma unroll 8
    for(int k=0;k<1024;k++)acc+=h[k*64+b]*Wf[(size_t)k*256+o];
    out[b*256+o]=acc;
}

extern "C" void kernel_launch(void* const* d_in,const int* in_sizes,int n_in,
                              void* d_out,int out_size){
    const float* x  =(const float*)d_in[0];
    const float* Wxz=(const float*)d_in[1];
    const float* Whz=(const float*)d_in[2];
    const float* Wxr=(const float*)d_in[3];
    const float* Whr=(const float*)d_in[4];
    const float* Wxh=(const float*)d_in[5];
    const float* Whh=(const float*)d_in[6];
    const float* bz =(const float*)d_in[7];
    const float* br =(const float*)d_in[8];
    const float* bh =(const float*)d_in[9];
    const float* Wf =(const float*)d_in[10];
    const float* bf =(const float*)d_in[11];
    float* out=(float*)d_out;

    dim3 gx(48,512);
    xproj_kernel<<<gx,256>>>(x,Wxz,Wxr,Wxh,bz,br,bh);
    cudaFuncSetAttribute(gru_kernel,cudaFuncAttributeMaxDynamicSharedMemorySize,SMEM_BYTES);
    gru_kernel<<<NBLK,NTHR,SMEM_BYTES>>>(Whz,Whr,Whh,0);
    gru_kernel<<<NBLK,NTHR,SMEM_BYTES>>>(Whz,Whr,Whh,256);
    head_kernel<<<64,256>>>(Wf,bf,out);
}

// round 12
// speedup vs baseline: 1.4133x; 1.4133x over previous
#include <cuda_runtime.h>
#include <cuda_bf16.h>
#include <cstdint>

#define NBLK 128
#define NTHR 256
typedef unsigned u32;
typedef unsigned long long u64;

// -------- device scratch --------
__device__ float d_XP[(size_t)64 * 512 * 3072];   // x-projections (+bias) [b*512+s][3072]
__device__ float d_hF[2][1024 * 64];              // h fp32 [col][b], double buffered
__device__ float d_z[1024 * 64];                  // z fp32 [col][b]
// k-blocked split-bf16 state: one contiguous blob per k-group for cp.async.bulk
__device__ __align__(16) unsigned short d_hA[4][2][64][266];   // [kg][hi|lo][b][k'&255]
__device__ __align__(16) unsigned short d_rhB[8][2][64][138];  // [kgB][hi|lo][b][k'&127]
__device__ float d_pA[(size_t)8 * 2048 * 64];     // phase-A partials [p][col][b]
__device__ float d_pB[(size_t)16 * 1024 * 64];    // phase-B partials [p][col][b]
__device__ unsigned d_count;

// smem offsets (u16 units)
#define WAHI 0
#define WALO 16896
#define WBHI 33792
#define WBLO 42496
#define STA   51200          // state buffer (A: [2][64][266]; B: [2][64][138])
#define STALO 68224          // STA + 64*266
#define STBLO 60032          // STA + 64*138
#define MBARO 85248          // mbarrier (byte off 170496)
#define SMEM_BYTES 170512
#define HA_BYTES 68096       // 2*64*266*2
#define RB_BYTES 35328       // 2*64*138*2

// -------- helpers --------
__device__ __forceinline__ u64 dup2(float x){u64 r;asm("mov.b64 %0,{%1,%1};":"=l"(r):"f"(x));return r;}
__device__ __forceinline__ void fma2(u64&a,u64 x,u64 y){asm("fma.rn.f32x2 %0,%1,%2,%0;":"+l"(a):"l"(x),"l"(y));}
__device__ __forceinline__ float2 unp2(u64 v){float2 f;asm("mov.b64 {%0,%1},%2;":"=f"(f.x),"=f"(f.y):"l"(v));return f;}
__device__ __forceinline__ void lds128(u64&a,u64&b,unsigned ad){asm volatile("ld.shared.v2.u64 {%0,%1},[%2];":"=l"(a),"=l"(b):"r"(ad));}
__device__ __forceinline__ float sigmoidf(float x){return 1.f/(1.f+__expf(-x));}

__device__ __forceinline__ void mma_bf16(float* c,const u32* a,const u32* b){
    asm volatile("mma.sync.aligned.m16n8k16.row.col.f32.bf16.bf16.f32 "
        "{%0,%1,%2,%3},{%4,%5,%6,%7},{%8,%9},{%0,%1,%2,%3};"
        : "+f"(c[0]),"+f"(c[1]),"+f"(c[2]),"+f"(c[3])
        : "r"(a[0]),"r"(a[1]),"r"(a[2]),"r"(a[3]),"r"(b[0]),"r"(b[1]));
}
__device__ __forceinline__ unsigned short bfhi(float x){
    return __bfloat16_as_ushort(__float2bfloat16(x));
}
__device__ __forceinline__ unsigned short bflo(float x){
    float h=__bfloat162float(__float2bfloat16(x));
    return __bfloat16_as_ushort(__float2bfloat16(x-h));
}
__device__ __forceinline__ u32 packu(unsigned short a,unsigned short b){
    return (u32)a|((u32)b<<16);
}

// grid barrier: async-proxy fence + release atomic; monotone counter
__device__ __forceinline__ void gridbar(){
    __syncthreads();
    if(threadIdx.x==0){
        asm volatile("fence.proxy.async;":::"memory");
        unsigned a;
        asm volatile("atom.add.release.gpu.u32 %0,[%1],%2;"
                     :"=r"(a):"l"(&d_count),"r"(1u):"memory");
        unsigned tg=a-(a&(NBLK-1))+NBLK,cur;
        do{asm volatile("ld.acquire.gpu.u32 %0,[%1];":"=r"(cur):"l"(&d_count));}while((int)(cur-tg)<0);
    }
    __syncthreads();
}

__device__ __forceinline__ void mbar_init(u32 mb,u32 c){
    asm volatile("mbarrier.init.shared.b64 [%0],%1;"::"r"(mb),"r"(c):"memory");
}
__device__ __forceinline__ void mbar_expect(u32 mb,u32 bytes){
    asm volatile("mbarrier.arrive.expect_tx.shared.b64 _,[%0],%1;"::"r"(mb),"r"(bytes):"memory");
}
__device__ __forceinline__ void bulk_copy(u32 dst,const void* src,u32 bytes,u32 mb){
    asm volatile("cp.async.bulk.shared::cta.global.mbarrier::complete_tx::bytes [%0],[%1],%2,[%3];"
        ::"r"(dst),"l"(src),"r"(bytes),"r"(mb):"memory");
}
__device__ __forceinline__ void mbar_wait(u32 mb,u32 par){
    u32 done;
    do{asm volatile("{\n\t.reg .pred p;\n\t"
        "mbarrier.try_wait.parity.acquire.cta.shared::cta.b64 p,[%1],%2,0x989680;\n\t"
        "selp.b32 %0,1,0,p;\n\t}":"=r"(done):"r"(mb),"r"(par):"memory");}while(!done);
}

// -------- xproj (fp32, proven) --------
__global__ void __launch_bounds__(256) xproj_kernel(
    const float* __restrict__ x,
    const float* __restrict__ Wxz,const float* __restrict__ Wxr,const float* __restrict__ Wxh,
    const float* __restrict__ bz,const float* __restrict__ br,const float* __restrict__ bh){
    __shared__ float As[64*68],Bs[64*68];
    const int tid=threadIdx.x,ct=blockIdx.x,rt=blockIdx.y,wsel=ct>>4;
    const float* W=(wsel==0)?Wxz:((wsel==1)?Wxr:Wxh);
    const float* bias=(wsel==0)?bz:((wsel==1)?br:bh);
    const int colbase=(ct&15)*64,row0=rt*64,r4=(tid>>4)*4,c4=(tid&15)*4;
    u64 acc[4][2]={};
    for(int k0=0;k0<256;k0+=64){
        __syncthreads();
#pragma unroll
        for(int i=0;i<4;i++){int q=tid+i*256,rr=q>>4,kq=q&15;
            *(float4*)&As[rr*68+kq*4]=*(const float4*)&x[(size_t)(row0+rr)*256+k0+kq*4];}
#pragma unroll
        for(int i=0;i<4;i++){int q=tid+i*256,kk=q>>4,cq=q&15;
            *(float4*)&Bs[kk*68+cq*4]=*(const float4*)&W[(size_t)(k0+kk)*1024+colbase+cq*4];}
        __syncthreads();
        unsigned bs=(unsigned)__cvta_generic_to_shared(&Bs[c4]);
#pragma unroll 8
        for(int kk=0;kk<64;kk++){
            u64 bL,bH;lds128(bL,bH,bs+kk*68*4);
#pragma unroll
            for(int i=0;i<4;i++){u64 ad=dup2(As[(r4+i)*68+kk]);fma2(acc[i][0],ad,bL);fma2(acc[i][1],ad,bH);}
        }
    }
    float4 bb=*(const float4*)&bias[colbase+c4];
#pragma unroll
    for(int i=0;i<4;i++){
        float2 lo=unp2(acc[i][0]),hi=unp2(acc[i][1]);
        *(float4*)&d_XP[(size_t)(row0+r4+i)*3072+ct*64+c4]=make_float4(lo.x+bb.x,lo.y+bb.y,hi.x+bb.z,hi.y+bb.w);
    }
}

// -------- persistent GRU: HMMA split-bf16, K-split blocks, bulk-copy staging --------
__global__ void __launch_bounds__(NTHR,1) gru_kernel(
    const float* __restrict__ Whz,const float* __restrict__ Whr,const float* __restrict__ Whh){
    extern __shared__ unsigned short sm[];
    const int tid=threadIdx.x,bid=blockIdx.x,wid=tid>>5,lane=tid&31;
    const int cg=bid&31, kg=bid>>5;    // phase A: 32 col-groups(64) x 4 k-groups(256)
    const int cgB=bid&15,kgB=bid>>4;   // phase B: 16 col-groups(64) x 8 k-groups(128)
    u32 smb; asm("{ .reg .u64 t; cvta.to.shared.u64 t,%1; cvt.u32.u64 %0,t; }":"=r"(smb):"l"((void*)sm));
    const u32 mbar=smb+MBARO*2;
    const u32 sta=smb+STA*2;

    // ---- load resident weight slices (split bf16, [col][k]+pad) ----
    {
        const int colg0=cg*64;
        const float* W=(colg0<1024)?(Whz+colg0):(Whr+colg0-1024);
#pragma unroll 4
        for(int i=0;i<64;i++){
            int idx=tid+i*NTHR,col=idx&63,k=idx>>6;
            float w=__ldg(&W[(size_t)(kg*256+k)*1024+col]);
            sm[WAHI+col*264+k]=bfhi(w);
            sm[WALO+col*264+k]=bflo(w);
        }
#pragma unroll 4
        for(int i=0;i<32;i++){
            int idx=tid+i*NTHR,col=idx&63,k=idx>>6;
            float w=__ldg(&Whh[(size_t)(kgB*128+k)*1024+cgB*64+col]);
            sm[WBHI+col*136+k]=bfhi(w);
            sm[WBLO+col*136+k]=bflo(w);
        }
    }
    // ---- zero h state (fp32 + blocked bf16, incl. pads) ----
    {
        int gid=bid*NTHR+tid;
        ((float2*)d_hF[0])[gid]=make_float2(0.f,0.f);
        u32* ha=(u32*)d_hA;
        for(int i=gid;i<68096;i+=NBLK*NTHR)ha[i]=0u;
    }
    if(tid==0)mbar_init(mbar,1);
    __syncthreads();
    gridbar();

    const int mw=wid&1,nw=(wid>>1)&1,kw=wid>>2;
    const int g=lane>>2,tk=(lane&3)*2;
    const int ecpA=tid>>5, ebA=(tid*2)&63;
    const int cA0=bid*16+ecpA*2;
    const int ecB=bid*8+wid, eb=lane*2;
    u32 par=0;

    for(int s=0;s<512;s++){
        const int cur=s&1,nxt=cur^1;
        // ---- stage h slice via one bulk copy ----
        if(tid==0){
            mbar_expect(mbar,HA_BYTES);
            bulk_copy(sta,&d_hA[kg][0][0][0],HA_BYTES,mbar);
        }
        // prefetch epilogue-A operands (cols cA0, cA0+1; batches ebA, ebA+1)
        float2 xpa=*(const float2*)&d_XP[((size_t)ebA*512+s)*3072+cA0];
        float2 xpb=*(const float2*)&d_XP[((size_t)(ebA+1)*512+s)*3072+cA0];
        float2 hA0=make_float2(0.f,0.f),hA1=hA0;
        if(bid>=64){
            hA0=__ldcg((const float2*)&d_hF[cur][(cA0-1024)*64+ebA]);
            hA1=__ldcg((const float2*)&d_hF[cur][(cA0-1023)*64+ebA]);
        }
        mbar_wait(mbar,par); par^=1;
        // ---- phase A MMA: warp m32n32, k-slice kw*128 ----
        float c[2][4][4];
#pragma unroll
        for(int mt=0;mt<2;mt++)
#pragma unroll
        for(int nt=0;nt<4;nt++)
#pragma unroll
        for(int q=0;q<4;q++)c[mt][nt][q]=0.f;
#pragma unroll 1
        for(int i=0;i<8;i++){
            int kk=kw*128+i*16+tk;
            u32 ah[2][4],al[2][4],bh[4][2],bl[4][2];
#pragma unroll
            for(int mt=0;mt<2;mt++){
                int r=mw*32+mt*16+g;
                ah[mt][0]=*(const u32*)&sm[WAHI+r*264+kk];
                ah[mt][1]=*(const u32*)&sm[WAHI+(r+8)*264+kk];
                ah[mt][2]=*(const u32*)&sm[WAHI+r*264+kk+8];
                ah[mt][3]=*(const u32*)&sm[WAHI+(r+8)*264+kk+8];
                al[mt][0]=*(const u32*)&sm[WALO+r*264+kk];
                al[mt][1]=*(const u32*)&sm[WALO+(r+8)*264+kk];
                al[mt][2]=*(const u32*)&sm[WALO+r*264+kk+8];
                al[mt][3]=*(const u32*)&sm[WALO+(r+8)*264+kk+8];
            }
#pragma unroll
            for(int nt=0;nt<4;nt++){
                int b=nw*32+nt*8+g;
                bh[nt][0]=*(const u32*)&sm[STA+b*266+kk];
                bh[nt][1]=*(const u32*)&sm[STA+b*266+kk+8];
                bl[nt][0]=*(const u32*)&sm[STALO+b*266+kk];
                bl[nt][1]=*(const u32*)&sm[STALO+b*266+kk+8];
            }
#pragma unroll
            for(int mt=0;mt<2;mt++)
#pragma unroll
            for(int nt=0;nt<4;nt++){
                mma_bf16(c[mt][nt],ah[mt],bh[nt]);
                mma_bf16(c[mt][nt],ah[mt],bl[nt]);
                mma_bf16(c[mt][nt],al[mt],bh[nt]);
            }
        }
        {
            int p=kg*2+kw;
#pragma unroll
            for(int mt=0;mt<2;mt++){
                int col=cg*64+mw*32+mt*16+g;
#pragma unroll
                for(int nt=0;nt<4;nt++){
                    int b=nw*32+nt*8+tk;
                    *(float2*)&d_pA[((size_t)p*2048+col)*64+b]=make_float2(c[mt][nt][0],c[mt][nt][1]);
                    *(float2*)&d_pA[((size_t)p*2048+col+8)*64+b]=make_float2(c[mt][nt][2],c[mt][nt][3]);
                }
            }
        }
        gridbar();
        // ---- epilogue A: sum 8 partials -> sigmoid -> z or rh ----
        {
            float s0=0.f,s1=0.f,s2=0.f,s3=0.f;
#pragma unroll
            for(int p=0;p<8;p++){
                float2 v0=__ldcg((const float2*)&d_pA[((size_t)p*2048+cA0)*64+ebA]);
                float2 v1=__ldcg((const float2*)&d_pA[((size_t)p*2048+cA0+1)*64+ebA]);
                s0+=v0.x;s1+=v0.y;s2+=v1.x;s3+=v1.y;
            }
            float v00=sigmoidf(s0+xpa.x),v01=sigmoidf(s1+xpb.x);
            float v10=sigmoidf(s2+xpa.y),v11=sigmoidf(s3+xpb.y);
            if(bid<64){
                *(float2*)&d_z[cA0*64+ebA]      =make_float2(v00,v01);
                *(float2*)&d_z[(cA0+1)*64+ebA]  =make_float2(v10,v11);
            }else{
                int cp0=cA0-1024;
                int kgr=cp0>>7,k2=cp0&127;
                float r00=v00*hA0.x,r01=v01*hA0.y;   // col cp0, b ebA / ebA+1
                float r10=v10*hA1.x,r11=v11*hA1.y;   // col cp0+1
                *(u32*)&d_rhB[kgr][0][ebA][k2]  =packu(bfhi(r00),bfhi(r10));
                *(u32*)&d_rhB[kgr][0][ebA+1][k2]=packu(bfhi(r01),bfhi(r11));
                *(u32*)&d_rhB[kgr][1][ebA][k2]  =packu(bflo(r00),bflo(r10));
                *(u32*)&d_rhB[kgr][1][ebA+1][k2]=packu(bflo(r01),bflo(r11));
            }
        }
        gridbar();
        // ---- stage rh slice via one bulk copy ----
        if(tid==0){
            mbar_expect(mbar,RB_BYTES);
            bulk_copy(sta,&d_rhB[kgB][0][0][0],RB_BYTES,mbar);
        }
        // prefetch epilogue-B operands
        float xq0=__ldg(&d_XP[((size_t)eb*512+s)*3072+2048+ecB]);
        float xq1=__ldg(&d_XP[((size_t)(eb+1)*512+s)*3072+2048+ecB]);
        float2 zv=__ldcg((const float2*)&d_z[ecB*64+eb]);
        float2 hv=__ldcg((const float2*)&d_hF[cur][ecB*64+eb]);
        mbar_wait(mbar,par); par^=1;
        // ---- phase B MMA: warp m32n32, k-slice kw*64 ----
        float cb[2][4][4];
#pragma unroll
        for(int mt=0;mt<2;mt++)
#pragma unroll
        for(int nt=0;nt<4;nt++)
#pragma unroll
        for(int q=0;q<4;q++)cb[mt][nt][q]=0.f;
#pragma unroll 1
        for(int i=0;i<4;i++){
            int kk=kw*64+i*16+tk;
            u32 ah[2][4],al[2][4],bh[4][2],bl[4][2];
#pragma unroll
            for(int mt=0;mt<2;mt++){
                int r=mw*32+mt*16+g;
                ah[mt][0]=*(const u32*)&sm[WBHI+r*136+kk];
                ah[mt][1]=*(const u32*)&sm[WBHI+(r+8)*136+kk];
                ah[mt][2]=*(const u32*)&sm[WBHI+r*136+kk+8];
                ah[mt][3]=*(const u32*)&sm[WBHI+(r+8)*136+kk+8];
                al[mt][0]=*(const u32*)&sm[WBLO+r*136+kk];
                al[mt][1]=*(const u32*)&sm[WBLO+(r+8)*136+kk];
                al[mt][2]=*(const u32*)&sm[WBLO+r*136+kk+8];
                al[mt][3]=*(const u32*)&sm[WBLO+(r+8)*136+kk+8];
            }
#pragma unroll
            for(int nt=0;nt<4;nt++){
                int b=nw*32+nt*8+g;
                bh[nt][0]=*(const u32*)&sm[STA+b*138+kk];
                bh[nt][1]=*(const u32*)&sm[STA+b*138+kk+8];
                bl[nt][0]=*(const u32*)&sm[STBLO+b*138+kk];
                bl[nt][1]=*(const u32*)&sm[STBLO+b*138+kk+8];
            }
#pragma unroll
            for(int mt=0;mt<2;mt++)
#pragma unroll
            for(int nt=0;nt<4;nt++){
                mma_bf16(cb[mt][nt],ah[mt],bh[nt]);
                mma_bf16(cb[mt][nt],ah[mt],bl[nt]);
                mma_bf16(cb[mt][nt],al[mt],bh[nt]);
            }
        }
        {
            int p=kgB*2+kw;
#pragma unroll
            for(int mt=0;mt<2;mt++){
                int col=cgB*64+mw*32+mt*16+g;
#pragma unroll
                for(int nt=0;nt<4;nt++){
                    int b=nw*32+nt*8+tk;
                    *(float2*)&d_pB[((size_t)p*1024+col)*64+b]=make_float2(cb[mt][nt][0],cb[mt][nt][1]);
                    *(float2*)&d_pB[((size_t)p*1024+col+8)*64+b]=make_float2(cb[mt][nt][2],cb[mt][nt][3]);
                }
            }
        }
        gridbar();
        // ---- epilogue B: sum 16 partials -> tanh -> h update ----
        {
            float n0=0.f,n1=0.f;
#pragma unroll
            for(int p=0;p<16;p++){
                float2 v=__ldcg((const float2*)&d_pB[((size_t)p*1024+ecB)*64+eb]);
                n0+=v.x;n1+=v.y;
            }
            n0=tanhf(n0+xq0); n1=tanhf(n1+xq1);
            float h0=(1.f-zv.x)*hv.x+zv.x*n0;
            float h1=(1.f-zv.y)*hv.y+zv.y*n1;
            *(float2*)&d_hF[nxt][ecB*64+eb]=make_float2(h0,h1);
            int kgh=ecB>>8,k1=ecB&255;
            d_hA[kgh][0][eb][k1]=bfhi(h0);   d_hA[kgh][1][eb][k1]=bflo(h0);
            d_hA[kgh][0][eb+1][k1]=bfhi(h1); d_hA[kgh][1][eb+1][k1]=bflo(h1);
        }
        gridbar();
    }
}

// -------- head: out[b][o] = sum_k hF[0][k][b]*Wf[k][o] + bf[o] --------
__global__ void head_kernel(const float* __restrict__ Wf,const float* __restrict__ bf,float* __restrict__ out){
    const int b=blockIdx.x,o=threadIdx.x;
    const float* h=d_hF[0];   // after 512 steps final h is in buffer 0
    float acc=bf[o];
#pragma unroll 8
    for(int k=0;k<1024;k++)acc+=h[k*64+b]*Wf[(size_t)k*256+o];
    out[b*256+o]=acc;
}

extern "C" void kernel_launch(void* const* d_in,const int* in_sizes,int n_in,
                              void* d_out,int out_size){
    const float* x  =(const float*)d_in[0];
    const float* Wxz=(const float*)d_in[1];
    const float* Whz=(const float*)d_in[2];
    const float* Wxr=(const float*)d_in[3];
    const float* Whr=(const float*)d_in[4];
    const float* Wxh=(const float*)d_in[5];
    const float* Whh=(const float*)d_in[6];
    const float* bz =(const float*)d_in[7];
    const float* br =(const float*)d_in[8];
    const float* bh =(const float*)d_in[9];
    const float* Wf =(const float*)d_in[10];
    const float* bf =(const float*)d_in[11];
    float* out=(float*)d_out;

    dim3 gx(48,512);
    xproj_kernel<<<gx,256>>>(x,Wxz,Wxr,Wxh,bz,br,bh);
    cudaFuncSetAttribute(gru_kernel,cudaFuncAttributeMaxDynamicSharedMemorySize,SMEM_BYTES);
    gru_kernel<<<NBLK,NTHR,SMEM_BYTES>>>(Whz,Whr,Whh);
    head_kernel<<<64,256>>>(Wf,bf,out);
}

// round 13
// speedup vs baseline: 1.6901x; 1.1959x over previous
#include <cuda_runtime.h>
#include <cuda_fp16.h>
#include <cstdint>

#define NBLK 128
#define NTHR 256
typedef unsigned u32;
typedef unsigned long long u64;

// -------- device scratch --------
__device__ float d_XP[(size_t)64 * 512 * 3072];   // x-projections (+bias) [b*512+s][3072]
__device__ float d_hF[2][1024 * 64];              // h fp32 [col][b], double buffered
__device__ float d_z[1024 * 64];                  // z fp32 [col][b]
// k-blocked fp16 state (XOR-swizzled within rows), contiguous per k-group for bulk copy
__device__ __align__(16) unsigned short d_hA[4][64][256];   // [kg][b][k'&255]
__device__ __align__(16) unsigned short d_rhB[8][64][128];  // [kgB][b][k'&127]
__device__ float d_pA[(size_t)8 * 2048 * 64];     // phase-A partials [p][col][b]
__device__ float d_pB[(size_t)16 * 1024 * 64];    // phase-B partials [p][col][b]
__device__ unsigned d_count;

// smem offsets (u16 units)
#define WA 0            // weights A: [64 cols][256 k] fp16, swizzled
#define WB 16384        // weights B: [64 cols][128 k]
#define STA 24576       // state buffer: [64 b][256] (A) or [64 b][128] (B)
#define MBARO_BYTES 81920
#define SMEM_BYTES 81936
#define HA_BYTES 32768
#define RB_BYTES 16384

// -------- helpers --------
__device__ __forceinline__ u64 dup2(float x){u64 r;asm("mov.b64 %0,{%1,%1};":"=l"(r):"f"(x));return r;}
__device__ __forceinline__ void fma2(u64&a,u64 x,u64 y){asm("fma.rn.f32x2 %0,%1,%2,%0;":"+l"(a):"l"(x),"l"(y));}
__device__ __forceinline__ float2 unp2(u64 v){float2 f;asm("mov.b64 {%0,%1},%2;":"=f"(f.x),"=f"(f.y):"l"(v));return f;}
__device__ __forceinline__ void lds128(u64&a,u64&b,unsigned ad){asm volatile("ld.shared.v2.u64 {%0,%1},[%2];":"=l"(a),"=l"(b):"r"(ad));}
__device__ __forceinline__ float sigmoidf(float x){return 1.f/(1.f+__expf(-x));}

// fp16 MMA, fp32 accumulate
__device__ __forceinline__ void mma_f16(float* c,const u32* a,const u32* b){
    asm volatile("mma.sync.aligned.m16n8k16.row.col.f32.f16.f16.f32 "
        "{%0,%1,%2,%3},{%4,%5,%6,%7},{%8,%9},{%0,%1,%2,%3};"
        : "+f"(c[0]),"+f"(c[1]),"+f"(c[2]),"+f"(c[3])
        : "r"(a[0]),"r"(a[1]),"r"(a[2]),"r"(a[3]),"r"(b[0]),"r"(b[1]));
}
__device__ __forceinline__ unsigned short h16(float x){
    return __half_as_ushort(__float2half_rn(x));
}
__device__ __forceinline__ u32 packu(unsigned short a,unsigned short b){
    return (u32)a|((u32)b<<16);
}
// bank-conflict-free word swizzle: word index ^= (row&7)*4
__device__ __forceinline__ int swz(int row,int w){return w^((row&7)<<2);}

// grid barrier: async-proxy fence + release atomic; monotone counter
__device__ __forceinline__ void gridbar(){
    __syncthreads();
    if(threadIdx.x==0){
        asm volatile("fence.proxy.async;":::"memory");
        unsigned a;
        asm volatile("atom.add.release.gpu.u32 %0,[%1],%2;"
                     :"=r"(a):"l"(&d_count),"r"(1u):"memory");
        unsigned tg=a-(a&(NBLK-1))+NBLK,cur;
        do{asm volatile("ld.acquire.gpu.u32 %0,[%1];":"=r"(cur):"l"(&d_count));}while((int)(cur-tg)<0);
    }
    __syncthreads();
}

__device__ __forceinline__ void mbar_init(u32 mb,u32 c){
    asm volatile("mbarrier.init.shared.b64 [%0],%1;"::"r"(mb),"r"(c):"memory");
}
__device__ __forceinline__ void mbar_expect(u32 mb,u32 bytes){
    asm volatile("mbarrier.arrive.expect_tx.shared.b64 _,[%0],%1;"::"r"(mb),"r"(bytes):"memory");
}
__device__ __forceinline__ void bulk_copy(u32 dst,const void* src,u32 bytes,u32 mb){
    asm volatile("cp.async.bulk.shared::cta.global.mbarrier::complete_tx::bytes [%0],[%1],%2,[%3];"
        ::"r"(dst),"l"(src),"r"(bytes),"r"(mb):"memory");
}
__device__ __forceinline__ void mbar_wait(u32 mb,u32 par){
    u32 done;
    do{asm volatile("{\n\t.reg .pred p;\n\t"
        "mbarrier.try_wait.parity.acquire.cta.shared::cta.b64 p,[%1],%2,0x989680;\n\t"
        "selp.b32 %0,1,0,p;\n\t}":"=r"(done):"r"(mb),"r"(par):"memory");}while(!done);
}

// -------- xproj (fp32, proven) --------
__global__ void __launch_bounds__(256) xproj_kernel(
    const float* __restrict__ x,
    const float* __restrict__ Wxz,const float* __restrict__ Wxr,const float* __restrict__ Wxh,
    const float* __restrict__ bz,const float* __restrict__ br,const float* __restrict__ bh){
    __shared__ float As[64*68],Bs[64*68];
    const int tid=threadIdx.x,ct=blockIdx.x,rt=blockIdx.y,wsel=ct>>4;
    const float* W=(wsel==0)?Wxz:((wsel==1)?Wxr:Wxh);
    const float* bias=(wsel==0)?bz:((wsel==1)?br:bh);
    const int colbase=(ct&15)*64,row0=rt*64,r4=(tid>>4)*4,c4=(tid&15)*4;
    u64 acc[4][2]={};
    for(int k0=0;k0<256;k0+=64){
        __syncthreads();
#pragma unroll
        for(int i=0;i<4;i++){int q=tid+i*256,rr=q>>4,kq=q&15;
            *(float4*)&As[rr*68+kq*4]=*(const float4*)&x[(size_t)(row0+rr)*256+k0+kq*4];}
#pragma unroll
        for(int i=0;i<4;i++){int q=tid+i*256,kk=q>>4,cq=q&15;
            *(float4*)&Bs[kk*68+cq*4]=*(const float4*)&W[(size_t)(k0+kk)*1024+colbase+cq*4];}
        __syncthreads();
        unsigned bs=(unsigned)__cvta_generic_to_shared(&Bs[c4]);
#pragma unroll 8
        for(int kk=0;kk<64;kk++){
            u64 bL,bH;lds128(bL,bH,bs+kk*68*4);
#pragma unroll
            for(int i=0;i<4;i++){u64 ad=dup2(As[(r4+i)*68+kk]);fma2(acc[i][0],ad,bL);fma2(acc[i][1],ad,bH);}
        }
    }
    float4 bb=*(const float4*)&bias[colbase+c4];
#pragma unroll
    for(int i=0;i<4;i++){
        float2 lo=unp2(acc[i][0]),hi=unp2(acc[i][1]);
        *(float4*)&d_XP[(size_t)(row0+r4+i)*3072+ct*64+c4]=make_float4(lo.x+bb.x,lo.y+bb.y,hi.x+bb.z,hi.y+bb.w);
    }
}

// -------- persistent GRU: fp16 HMMA single-pass, K-split blocks, bulk-copy staging --------
__global__ void __launch_bounds__(NTHR,1) gru_kernel(
    const float* __restrict__ Whz,const float* __restrict__ Whr,const float* __restrict__ Whh){
    extern __shared__ unsigned short sm[];
    const int tid=threadIdx.x,bid=blockIdx.x,wid=tid>>5,lane=tid&31;
    const int cg=bid&31, kg=bid>>5;    // phase A: 32 col-groups(64) x 4 k-groups(256)
    const int cgB=bid&15,kgB=bid>>4;   // phase B: 16 col-groups(64) x 8 k-groups(128)
    u32 smb; asm("{ .reg .u64 t; cvta.to.shared.u64 t,%1; cvt.u32.u64 %0,t; }":"=r"(smb):"l"((void*)sm));
    const u32 mbar=smb+MBARO_BYTES;
    const u32 sta=smb+STA*2;

    // ---- load resident weight slices (fp16, swizzled [col][k]) ----
    {
        const int colg0=cg*64;
        const float* Wp=(colg0<1024)?(Whz+colg0):(Whr+colg0-1024);
#pragma unroll 4
        for(int i=0;i<64;i++){
            int idx=tid+i*NTHR,col=idx&63,k=idx>>6;
            float w=__ldg(&Wp[(size_t)(kg*256+k)*1024+col]);
            sm[WA+col*256+((swz(col,k>>1)<<1)|(k&1))]=h16(w);
        }
#pragma unroll 4
        for(int i=0;i<32;i++){
            int idx=tid+i*NTHR,col=idx&63,k=idx>>6;
            float w=__ldg(&Whh[(size_t)(kgB*128+k)*1024+cgB*64+col]);
            sm[WB+col*128+((swz(col,k>>1)<<1)|(k&1))]=h16(w);
        }
    }
    // ---- zero h state (fp32 + fp16 blocked) ----
    {
        int gid=bid*NTHR+tid;
        ((float2*)d_hF[0])[gid]=make_float2(0.f,0.f);
        ((u32*)d_hA)[gid]=0u;   // 128*256 = 32768 u32 = whole d_hA
    }
    if(tid==0)mbar_init(mbar,1);
    __syncthreads();
    gridbar();

    const int mw=wid&1,nw=(wid>>1)&1,kw=wid>>2;
    const int g=lane>>2,tk=(lane&3)*2;
    const int ecpA=tid>>5, ebA=(tid*2)&63;
    const int cA0=bid*16+ecpA*2;
    const int ecB=bid*8+wid, eb=lane*2;
    u32 par=0;

    for(int s=0;s<512;s++){
        const int cur=s&1,nxt=cur^1;
        // ---- stage h slice via one bulk copy ----
        if(tid==0){
            mbar_expect(mbar,HA_BYTES);
            bulk_copy(sta,&d_hA[kg][0][0],HA_BYTES,mbar);
        }
        // prefetch epilogue-A operands
        float2 xpa=*(const float2*)&d_XP[((size_t)ebA*512+s)*3072+cA0];
        float2 xpb=*(const float2*)&d_XP[((size_t)(ebA+1)*512+s)*3072+cA0];
        float2 hA0=make_float2(0.f,0.f),hA1=hA0;
        if(bid>=64){
            hA0=__ldcg((const float2*)&d_hF[cur][(cA0-1024)*64+ebA]);
            hA1=__ldcg((const float2*)&d_hF[cur][(cA0-1023)*64+ebA]);
        }
        mbar_wait(mbar,par); par^=1;
        // ---- phase A MMA: warp m32n32, k-slice kw*128 ----
        float c[2][4][4];
#pragma unroll
        for(int mt=0;mt<2;mt++)
#pragma unroll
        for(int nt=0;nt<4;nt++)
#pragma unroll
        for(int q=0;q<4;q++)c[mt][nt][q]=0.f;
#pragma unroll 1
        for(int i=0;i<8;i++){
            int kk=kw*128+i*16+tk;
            int w0=kk>>1,w1=w0+4;
            u32 a[2][4],bfr[4][2];
#pragma unroll
            for(int mt=0;mt<2;mt++){
                int r=mw*32+mt*16+g;
                a[mt][0]=*(const u32*)&sm[WA+r*256+(swz(r,w0)<<1)];
                a[mt][1]=*(const u32*)&sm[WA+(r+8)*256+(swz(r+8,w0)<<1)];
                a[mt][2]=*(const u32*)&sm[WA+r*256+(swz(r,w1)<<1)];
                a[mt][3]=*(const u32*)&sm[WA+(r+8)*256+(swz(r+8,w1)<<1)];
            }
#pragma unroll
            for(int nt=0;nt<4;nt++){
                int b=nw*32+nt*8+g;
                bfr[nt][0]=*(const u32*)&sm[STA+b*256+(swz(b,w0)<<1)];
                bfr[nt][1]=*(const u32*)&sm[STA+b*256+(swz(b,w1)<<1)];
            }
#pragma unroll
            for(int mt=0;mt<2;mt++)
#pragma unroll
            for(int nt=0;nt<4;nt++)
                mma_f16(c[mt][nt],a[mt],bfr[nt]);
        }
        {
            int p=kg*2+kw;
#pragma unroll
            for(int mt=0;mt<2;mt++){
                int col=cg*64+mw*32+mt*16+g;
#pragma unroll
                for(int nt=0;nt<4;nt++){
                    int b=nw*32+nt*8+tk;
                    *(float2*)&d_pA[((size_t)p*2048+col)*64+b]=make_float2(c[mt][nt][0],c[mt][nt][1]);
                    *(float2*)&d_pA[((size_t)p*2048+col+8)*64+b]=make_float2(c[mt][nt][2],c[mt][nt][3]);
                }
            }
        }
        gridbar();
        // ---- epilogue A: sum 8 partials -> sigmoid -> z or rh ----
        {
            float s0=0.f,s1=0.f,s2=0.f,s3=0.f;
#pragma unroll
            for(int p=0;p<8;p++){
                float2 v0=__ldcg((const float2*)&d_pA[((size_t)p*2048+cA0)*64+ebA]);
                float2 v1=__ldcg((const float2*)&d_pA[((size_t)p*2048+cA0+1)*64+ebA]);
                s0+=v0.x;s1+=v0.y;s2+=v1.x;s3+=v1.y;
            }
            float v00=sigmoidf(s0+xpa.x),v01=sigmoidf(s1+xpb.x);
            float v10=sigmoidf(s2+xpa.y),v11=sigmoidf(s3+xpb.y);
            if(bid<64){
                *(float2*)&d_z[cA0*64+ebA]      =make_float2(v00,v01);
                *(float2*)&d_z[(cA0+1)*64+ebA]  =make_float2(v10,v11);
            }else{
                int cp0=cA0-1024;
                int kgr=cp0>>7,w=(cp0&127)>>1;   // cp0 even
                float r00=v00*hA0.x,r01=v01*hA0.y;   // col cp0,  b ebA / ebA+1
                float r10=v10*hA1.x,r11=v11*hA1.y;   // col cp0+1
                *(u32*)&d_rhB[kgr][ebA][swz(ebA,w)<<1]    =packu(h16(r00),h16(r10));
                *(u32*)&d_rhB[kgr][ebA+1][swz(ebA+1,w)<<1]=packu(h16(r01),h16(r11));
            }
        }
        gridbar();
        // ---- stage rh slice via one bulk copy ----
        if(tid==0){
            mbar_expect(mbar,RB_BYTES);
            bulk_copy(sta,&d_rhB[kgB][0][0],RB_BYTES,mbar);
        }
        // prefetch epilogue-B operands
        float xq0=__ldg(&d_XP[((size_t)eb*512+s)*3072+2048+ecB]);
        float xq1=__ldg(&d_XP[((size_t)(eb+1)*512+s)*3072+2048+ecB]);
        float2 zv=__ldcg((const float2*)&d_z[ecB*64+eb]);
        float2 hv=__ldcg((const float2*)&d_hF[cur][ecB*64+eb]);
        mbar_wait(mbar,par); par^=1;
        // ---- phase B MMA: warp m32n32, k-slice kw*64 ----
        float cb[2][4][4];
#pragma unroll
        for(int mt=0;mt<2;mt++)
#pragma unroll
        for(int nt=0;nt<4;nt++)
#pragma unroll
        for(int q=0;q<4;q++)cb[mt][nt][q]=0.f;
#pragma unroll 1
        for(int i=0;i<4;i++){
            int kk=kw*64+i*16+tk;
            int w0=kk>>1,w1=w0+4;
            u32 a[2][4],bfr[4][2];
#pragma unroll
            for(int mt=0;mt<2;mt++){
                int r=mw*32+mt*16+g;
                a[mt][0]=*(const u32*)&sm[WB+r*128+(swz(r,w0)<<1)];
                a[mt][1]=*(const u32*)&sm[WB+(r+8)*128+(swz(r+8,w0)<<1)];
                a[mt][2]=*(const u32*)&sm[WB+r*128+(swz(r,w1)<<1)];
                a[mt][3]=*(const u32*)&sm[WB+(r+8)*128+(swz(r+8,w1)<<1)];
            }
#pragma unroll
            for(int nt=0;nt<4;nt++){
                int b=nw*32+nt*8+g;
                bfr[nt][0]=*(const u32*)&sm[STA+b*128+(swz(b,w0)<<1)];
                bfr[nt][1]=*(const u32*)&sm[STA+b*128+(swz(b,w1)<<1)];
            }
#pragma unroll
            for(int mt=0;mt<2;mt++)
#pragma unroll
            for(int nt=0;nt<4;nt++)
                mma_f16(cb[mt][nt],a[mt],bfr[nt]);
        }
        {
            int p=kgB*2+kw;
#pragma unroll
            for(int mt=0;mt<2;mt++){
                int col=cgB*64+mw*32+mt*16+g;
#pragma unroll
                for(int nt=0;nt<4;nt++){
                    int b=nw*32+nt*8+tk;
                    *(float2*)&d_pB[((size_t)p*1024+col)*64+b]=make_float2(cb[mt][nt][0],cb[mt][nt][1]);
                    *(float2*)&d_pB[((size_t)p*1024+col+8)*64+b]=make_float2(cb[mt][nt][2],cb[mt][nt][3]);
                }
            }
        }
        gridbar();
        // ---- epilogue B: sum 16 partials -> tanh -> h update ----
        {
            float n0=0.f,n1=0.f;
#pragma unroll
            for(int p=0;p<16;p++){
                float2 v=__ldcg((const float2*)&d_pB[((size_t)p*1024+ecB)*64+eb]);
                n0+=v.x;n1+=v.y;
            }
            n0=tanhf(n0+xq0); n1=tanhf(n1+xq1);
            float h0=(1.f-zv.x)*hv.x+zv.x*n0;
            float h1=(1.f-zv.y)*hv.y+zv.y*n1;
            *(float2*)&d_hF[nxt][ecB*64+eb]=make_float2(h0,h1);
            int kgh=ecB>>8,k1=ecB&255;
            d_hA[kgh][eb][(swz(eb,k1>>1)<<1)|(k1&1)]  =h16(h0);
            d_hA[kgh][eb+1][(swz(eb+1,k1>>1)<<1)|(k1&1)]=h16(h1);
        }
        gridbar();
    }
}

// -------- head: out[b][o] = sum_k hF[0][k][b]*Wf[k][o] + bf[o] --------
__global__ void head_kernel(const float* __restrict__ Wf,const float* __restrict__ bf,float* __restrict__ out){
    const int b=blockIdx.x,o=threadIdx.x;
    const float* h=d_hF[0];   // after 512 steps final h is in buffer 0
    float acc=bf[o];
#pragma unroll 8
    for(int k=0;k<1024;k++)acc+=h[k*64+b]*Wf[(size_t)k*256+o];
    out[b*256+o]=acc;
}

extern "C" void kernel_launch(void* const* d_in,const int* in_sizes,int n_in,
                              void* d_out,int out_size){
    const float* x  =(const float*)d_in[0];
    const float* Wxz=(const float*)d_in[1];
    const float* Whz=(const float*)d_in[2];
    const float* Wxr=(const float*)d_in[3];
    const float* Whr=(const float*)d_in[4];
    const float* Wxh=(const float*)d_in[5];
    const float* Whh=(const float*)d_in[6];
    const float* bz =(const float*)d_in[7];
    const float* br =(const float*)d_in[8];
    const float* bh =(const float*)d_in[9];
    const float* Wf =(const float*)d_in[10];
    const float* bf =(const float*)d_in[11];
    float* out=(float*)d_out;

    dim3 gx(48,512);
    xproj_kernel<<<gx,256>>>(x,Wxz,Wxr,Wxh,bz,br,bh);
    cudaFuncSetAttribute(gru_kernel,cudaFuncAttributeMaxDynamicSharedMemorySize,SMEM_BYTES);
    gru_kernel<<<NBLK,NTHR,SMEM_BYTES>>>(Whz,Whr,Whh);
    head_kernel<<<64,256>>>(Wf,bf,out);
}